// round 1
// baseline (speedup 1.0000x reference)
#include <cuda_runtime.h>
#include <cuda_bf16.h>
#include <math.h>

#define NN   30000
#define EE   120000
#define N2   15000
#define N3   7500
#define GG   512
#define YW   1664   // 26*64 (25 hidden rows + 1 bias row)

// ---------------- scratch (static device allocations) ----------------
__device__ float d_acc1[NN * 32];
__device__ int   d_cnt1[NN];
__device__ float d_h[NN * 32];
__device__ float d_x2[N2 * 32];
__device__ float d_pos2[N2 * 2];
__device__ float d_cart[EE * 2];
__device__ int   d_maxbits;
__device__ float d_y[N2 * YW];
__device__ float d_acc2[N2 * 64];
__device__ int   d_cnt2[N2];
__device__ float d_h2[N2 * 64];
__device__ float d_gsum[GG * 64];
__device__ int   d_gcnt[GG];

__device__ __forceinline__ float eluf(float x) { return x > 0.f ? x : expm1f(x); }

// ---------------- K0: zero accumulators ----------------
__global__ void k_zero() {
    int i = blockIdx.x * blockDim.x + threadIdx.x;
    int stride = gridDim.x * blockDim.x;
    for (int j = i; j < NN * 32; j += stride) d_acc1[j] = 0.f;
    for (int j = i; j < N2 * 64; j += stride) d_acc2[j] = 0.f;
    for (int j = i; j < NN; j += stride) d_cnt1[j] = 0;
    for (int j = i; j < N2; j += stride) d_cnt2[j] = 0;
    for (int j = i; j < GG * 64; j += stride) d_gsum[j] = 0.f;
    for (int j = i; j < GG; j += stride) d_gcnt[j] = 0;
    if (i == 0) d_maxbits = 0;
}

// ---------------- K1: layer-1 edge kernel (warp per edge) ----------------
__global__ void k_edge1(const float* __restrict__ x, const float* __restrict__ ea,
                        const float* __restrict__ w1a, const float* __restrict__ b1a,
                        const float* __restrict__ w1b, const float* __restrict__ b1b,
                        const int* __restrict__ ei) {
    int warp = (blockIdx.x * blockDim.x + threadIdx.x) >> 5;
    int lane = threadIdx.x & 31;
    if (warp >= EE) return;
    int src = ei[warp];
    int dst = ei[EE + warp];
    float e0 = __ldg(ea + warp * 2);
    float e1 = __ldg(ea + warp * 2 + 1);
    float hid[25];
#pragma unroll
    for (int h = 0; h < 25; h++) {
        float v = fmaf(e0, __ldg(w1a + h), fmaf(e1, __ldg(w1a + 25 + h), __ldg(b1a + h)));
        hid[h] = fmaxf(v, 0.f);
    }
    float s = __ldg(b1b + lane);
#pragma unroll
    for (int h = 0; h < 25; h++)
        s = fmaf(hid[h], __ldg(w1b + h * 32 + lane), s);
    float xs = __ldg(x + src);
    atomicAdd(d_acc1 + dst * 32 + lane, xs * s);
    if (lane == 0) atomicAdd(d_cnt1 + dst, 1);
}

// ---------------- K2: layer-1 node update ----------------
__global__ void k_node1(const float* __restrict__ x, const float* __restrict__ root1,
                        const float* __restrict__ bias1) {
    int idx = blockIdx.x * blockDim.x + threadIdx.x;
    if (idx >= NN * 32) return;
    int n = idx >> 5, o = idx & 31;
    float c = fmaxf((float)d_cnt1[n], 1.f);
    float v = d_acc1[idx] / c + __ldg(x + n) * __ldg(root1 + o) + __ldg(bias1 + o);
    d_h[idx] = eluf(v);
}

// ---------------- K3: pool 1 (pairwise max) + pos2 (pairwise mean) ----------------
__global__ void k_pool1(const float* __restrict__ pos) {
    int idx = blockIdx.x * blockDim.x + threadIdx.x;
    if (idx >= N2 * 32) return;
    int p = idx >> 5, o = idx & 31;
    d_x2[idx] = fmaxf(d_h[(2 * p) * 32 + o], d_h[(2 * p + 1) * 32 + o]);
    if (o < 2)
        d_pos2[p * 2 + o] = 0.5f * (pos[(2 * p) * 2 + o] + pos[(2 * p + 1) * 2 + o]);
}

// ---------------- K4: edge geometry + global abs-max ----------------
__global__ void k_geom(const int* __restrict__ ei) {
    int t = blockIdx.x * blockDim.x + threadIdx.x;
    float m = 0.f;
    if (t < EE) {
        int r2 = ei[t] >> 1, c2 = ei[EE + t] >> 1;
        float cx = 0.f, cy = 0.f;
        if (r2 != c2) {
            cx = d_pos2[c2 * 2]     - d_pos2[r2 * 2];
            cy = d_pos2[c2 * 2 + 1] - d_pos2[r2 * 2 + 1];
        }
        d_cart[t * 2] = cx;
        d_cart[t * 2 + 1] = cy;
        m = fmaxf(fabsf(cx), fabsf(cy));
    }
#pragma unroll
    for (int off = 16; off > 0; off >>= 1)
        m = fmaxf(m, __shfl_down_sync(0xffffffffu, m, off));
    if ((threadIdx.x & 31) == 0)
        atomicMax(&d_maxbits, __float_as_int(m)); // nonneg floats: int order == float order
}

// ---------------- K5: y GEMM: (15000x32) @ (32x1664) ----------------
// y[r, h*64+o] = sum_i x2[r,i]*w2b[h,i*64+o]  (h<25);  y[r,25*64+o] = sum_i x2[r,i]*b2b[i*64+o]
__global__ void k_ygemm(const float* __restrict__ w2b, const float* __restrict__ b2b) {
    __shared__ float As[32][65];   // [k][m], padded
    __shared__ float Bs[32][64];   // [k][n]
    int tid = threadIdx.x;
    int tx = tid & 15, ty = tid >> 4;
    int m0 = blockIdx.y * 64, n0 = blockIdx.x * 64;
    for (int i = tid; i < 64 * 32; i += 256) {
        int m = i >> 5, k = i & 31;
        int gm = m0 + m;
        As[k][m] = (gm < N2) ? d_x2[gm * 32 + k] : 0.f;
    }
    for (int i = tid; i < 32 * 64; i += 256) {
        int k = i >> 6, n = i & 63;
        int j = n0 + n;
        int h = j >> 6, o = j & 63;
        Bs[k][n] = (h < 25) ? __ldg(w2b + h * 2048 + k * 64 + o)
                            : __ldg(b2b + k * 64 + o);
    }
    __syncthreads();
    float acc[4][4] = {};
#pragma unroll
    for (int k = 0; k < 32; k++) {
        float a[4], b[4];
#pragma unroll
        for (int m = 0; m < 4; m++) a[m] = As[k][ty * 4 + m];
#pragma unroll
        for (int n = 0; n < 4; n++) b[n] = Bs[k][tx * 4 + n];
#pragma unroll
        for (int m = 0; m < 4; m++)
#pragma unroll
            for (int n = 0; n < 4; n++) acc[m][n] = fmaf(a[m], b[n], acc[m][n]);
    }
#pragma unroll
    for (int m = 0; m < 4; m++) {
        int gm = m0 + ty * 4 + m;
        if (gm < N2) {
#pragma unroll
            for (int n = 0; n < 4; n++)
                d_y[gm * YW + n0 + tx * 4 + n] = acc[m][n];
        }
    }
}

// ---------------- K6: layer-2 edge kernel (warp per edge) ----------------
__global__ void k_edge2(const int* __restrict__ ei, const float* __restrict__ w2a,
                        const float* __restrict__ b2a) {
    int warp = (blockIdx.x * blockDim.x + threadIdx.x) >> 5;
    int lane = threadIdx.x & 31;
    if (warp >= EE) return;
    int r2 = ei[warp] >> 1, c2 = ei[EE + warp] >> 1;
    if (r2 == c2) return;  // masked edges go to the discarded dummy segment
    float maxv = __int_as_float(d_maxbits);
    float inv = 0.5f / maxv;
    float ea0 = fmaf(d_cart[warp * 2],     inv, 0.5f);
    float ea1 = fmaf(d_cart[warp * 2 + 1], inv, 0.5f);
    float hid[25];
#pragma unroll
    for (int h = 0; h < 25; h++) {
        float v = fmaf(ea0, __ldg(w2a + h), fmaf(ea1, __ldg(w2a + 25 + h), __ldg(b2a + h)));
        hid[h] = fmaxf(v, 0.f);
    }
    const float* yr = d_y + r2 * YW;
#pragma unroll
    for (int part = 0; part < 2; part++) {
        int o = lane + part * 32;
        float s = yr[25 * 64 + o];
#pragma unroll
        for (int h = 0; h < 25; h++)
            s = fmaf(hid[h], yr[h * 64 + o], s);
        atomicAdd(d_acc2 + c2 * 64 + o, s);
    }
    if (lane == 0) atomicAdd(d_cnt2 + c2, 1);
}

// ---------------- K7: layer-2 node update ----------------
__global__ void k_node2(const float* __restrict__ root2, const float* __restrict__ bias2) {
    int idx = blockIdx.x * blockDim.x + threadIdx.x;
    if (idx >= N2 * 64) return;
    int c = idx >> 6, o = idx & 63;
    float cnt = fmaxf((float)d_cnt2[c], 1.f);
    float v = d_acc2[idx] / cnt + __ldg(bias2 + o);
#pragma unroll
    for (int i = 0; i < 32; i++)
        v = fmaf(d_x2[c * 32 + i], __ldg(root2 + i * 64 + o), v);
    d_h2[idx] = eluf(v);
}

// ---------------- K8: pool 2 + global mean scatter ----------------
__global__ void k_pool2g(const int* __restrict__ batch) {
    int idx = blockIdx.x * blockDim.x + threadIdx.x;
    if (idx >= N3 * 64) return;
    int q = idx >> 6, o = idx & 63;
    float v = fmaxf(d_h2[(2 * q) * 64 + o], d_h2[(2 * q + 1) * 64 + o]);
    int g = __ldg(batch + 4 * q);   // batch3[q] = batch[4q]
    atomicAdd(d_gsum + g * 64 + o, v);
    if (o == 0) atomicAdd(d_gcnt + g, 1);
}

// ---------------- K9: MLP head + log_softmax (one block per graph) ----------------
__global__ void k_head(const float* __restrict__ fc1_w, const float* __restrict__ fc1_b,
                       const float* __restrict__ fc2_w, const float* __restrict__ fc2_b,
                       float* __restrict__ out) {
    int g = blockIdx.x;
    int t = threadIdx.x;
    __shared__ float m[64];
    __shared__ float a[128];
    __shared__ float logits[10];
    if (t < 64)
        m[t] = d_gsum[g * 64 + t] / fmaxf((float)d_gcnt[g], 1.f);
    __syncthreads();
    float aj = __ldg(fc1_b + t);
#pragma unroll
    for (int i = 0; i < 64; i++)
        aj = fmaf(m[i], __ldg(fc1_w + i * 128 + t), aj);
    a[t] = eluf(aj);
    __syncthreads();
    if (t < 10) {
        float l = __ldg(fc2_b + t);
#pragma unroll 8
        for (int j = 0; j < 128; j++)
            l = fmaf(a[j], __ldg(fc2_w + j * 10 + t), l);
        logits[t] = l;
    }
    __syncthreads();
    if (t == 0) {
        float mx = -1e30f;
#pragma unroll
        for (int k = 0; k < 10; k++) mx = fmaxf(mx, logits[k]);
        float se = 0.f;
#pragma unroll
        for (int k = 0; k < 10; k++) se += expf(logits[k] - mx);
        float lse = logf(se) + mx;
#pragma unroll
        for (int k = 0; k < 10; k++) out[g * 10 + k] = logits[k] - lse;
    }
}

// ---------------- launcher ----------------
extern "C" void kernel_launch(void* const* d_in, const int* in_sizes, int n_in,
                              void* d_out, int out_size) {
    const float* x      = (const float*)d_in[0];
    const float* eattr  = (const float*)d_in[1];
    const float* pos    = (const float*)d_in[2];
    const float* w1a    = (const float*)d_in[3];
    const float* b1a    = (const float*)d_in[4];
    const float* w1b    = (const float*)d_in[5];
    const float* b1b    = (const float*)d_in[6];
    const float* root1  = (const float*)d_in[7];
    const float* bias1  = (const float*)d_in[8];
    const float* w2a    = (const float*)d_in[9];
    const float* b2a    = (const float*)d_in[10];
    const float* w2b    = (const float*)d_in[11];
    const float* b2b    = (const float*)d_in[12];
    const float* root2  = (const float*)d_in[13];
    const float* bias2  = (const float*)d_in[14];
    const float* fc1_w  = (const float*)d_in[15];
    const float* fc1_b  = (const float*)d_in[16];
    const float* fc2_w  = (const float*)d_in[17];
    const float* fc2_b  = (const float*)d_in[18];
    const int*   ei     = (const int*)d_in[19];
    const int*   batch  = (const int*)d_in[20];
    float* out = (float*)d_out;

    k_zero<<<512, 256>>>();
    k_edge1<<<(EE * 32 + 255) / 256, 256>>>(x, eattr, w1a, b1a, w1b, b1b, ei);
    k_node1<<<(NN * 32 + 255) / 256, 256>>>(x, root1, bias1);
    k_pool1<<<(N2 * 32 + 255) / 256, 256>>>(pos);
    k_geom<<<(EE + 255) / 256, 256>>>(ei);
    {
        dim3 grid(YW / 64, (N2 + 63) / 64);
        k_ygemm<<<grid, 256>>>(w2b, b2b);
    }
    k_edge2<<<(EE * 32 + 255) / 256, 256>>>(ei, w2a, b2a);
    k_node2<<<(N2 * 64 + 255) / 256, 256>>>(root2, bias2);
    k_pool2g<<<(N3 * 64 + 255) / 256, 256>>>(batch);
    k_head<<<GG, 128>>>(fc1_w, fc1_b, fc2_w, fc2_b, out);
}

// round 2
// speedup vs baseline: 1.0010x; 1.0010x over previous
#include <cuda_runtime.h>
#include <cuda_bf16.h>
#include <math.h>

#define NN   30000
#define EE   120000
#define N2   15000
#define N3   7500
#define GG   512
#define YW   1664   // 26*64 (25 hidden rows + 1 bias row)

// ---------------- scratch (static device allocations) ----------------
__device__ float d_acc1[NN * 32];
__device__ int   d_cnt1[NN];
__device__ float d_x2[N2 * 32];
__device__ float d_pos2[N2 * 2];
__device__ float d_cart[EE * 2];
__device__ int   d_maxbits;
__device__ float d_y[N2 * YW];
__device__ float d_acc2[N2 * 64];
__device__ int   d_cnt2[N2];
__device__ float d_gsum[GG * 64];
__device__ int   d_gcnt[GG];
// CSR (edges grouped by layer-2 source node r2)
__device__ int   d_deg[N2];
__device__ int   d_off[N2];
__device__ int   d_cursor[N2];
__device__ int   d_edst[EE];        // destination c2 per CSR slot
__device__ float d_hid[EE * 25];    // relu MLP hidden per CSR slot

__device__ __forceinline__ float eluf(float x) { return x > 0.f ? x : expm1f(x); }

// ---------------- K0: zero accumulators ----------------
__global__ void k_zero() {
    int i = blockIdx.x * blockDim.x + threadIdx.x;
    int stride = gridDim.x * blockDim.x;
    for (int j = i; j < NN * 32; j += stride) d_acc1[j] = 0.f;
    for (int j = i; j < N2 * 64; j += stride) d_acc2[j] = 0.f;
    for (int j = i; j < NN; j += stride) d_cnt1[j] = 0;
    for (int j = i; j < N2; j += stride) { d_cnt2[j] = 0; d_deg[j] = 0; d_cursor[j] = 0; }
    for (int j = i; j < GG * 64; j += stride) d_gsum[j] = 0.f;
    for (int j = i; j < GG; j += stride) d_gcnt[j] = 0;
    if (i == 0) d_maxbits = 0;
}

// ---------------- K1: layer-1 edge kernel (warp per edge) ----------------
__global__ void k_edge1(const float* __restrict__ x, const float* __restrict__ ea,
                        const float* __restrict__ w1a, const float* __restrict__ b1a,
                        const float* __restrict__ w1b, const float* __restrict__ b1b,
                        const int* __restrict__ ei) {
    int warp = (blockIdx.x * blockDim.x + threadIdx.x) >> 5;
    int lane = threadIdx.x & 31;
    if (warp >= EE) return;
    int src = ei[warp];
    int dst = ei[EE + warp];
    float e0 = __ldg(ea + warp * 2);
    float e1 = __ldg(ea + warp * 2 + 1);
    float hid[25];
#pragma unroll
    for (int h = 0; h < 25; h++) {
        float v = fmaf(e0, __ldg(w1a + h), fmaf(e1, __ldg(w1a + 25 + h), __ldg(b1a + h)));
        hid[h] = fmaxf(v, 0.f);
    }
    float s = __ldg(b1b + lane);
#pragma unroll
    for (int h = 0; h < 25; h++)
        s = fmaf(hid[h], __ldg(w1b + h * 32 + lane), s);
    float xs = __ldg(x + src);
    atomicAdd(d_acc1 + dst * 32 + lane, xs * s);
    if (lane == 0) atomicAdd(d_cnt1 + dst, 1);
}

// ---------------- K2: fused layer-1 node update + pairwise max pool + pos mean ----------------
__global__ void k_node1pool(const float* __restrict__ x, const float* __restrict__ root1,
                            const float* __restrict__ bias1, const float* __restrict__ pos) {
    int idx = blockIdx.x * blockDim.x + threadIdx.x;
    if (idx >= N2 * 32) return;
    int p = idx >> 5, o = idx & 31;
    float v[2];
#pragma unroll
    for (int j = 0; j < 2; j++) {
        int n = 2 * p + j;
        float c = fmaxf((float)d_cnt1[n], 1.f);
        float t = d_acc1[n * 32 + o] / c + __ldg(x + n) * __ldg(root1 + o) + __ldg(bias1 + o);
        v[j] = eluf(t);
    }
    d_x2[idx] = fmaxf(v[0], v[1]);
    if (o < 2)
        d_pos2[p * 2 + o] = 0.5f * (pos[(2 * p) * 2 + o] + pos[(2 * p + 1) * 2 + o]);
}

// ---------------- K3: edge geometry + global abs-max + CSR degree + cnt2 ----------------
__global__ void k_geom(const int* __restrict__ ei) {
    int t = blockIdx.x * blockDim.x + threadIdx.x;
    float m = 0.f;
    if (t < EE) {
        int r2 = ei[t] >> 1, c2 = ei[EE + t] >> 1;
        float cx = 0.f, cy = 0.f;
        if (r2 != c2) {
            cx = d_pos2[c2 * 2]     - d_pos2[r2 * 2];
            cy = d_pos2[c2 * 2 + 1] - d_pos2[r2 * 2 + 1];
            atomicAdd(&d_deg[r2], 1);
            atomicAdd(&d_cnt2[c2], 1);
        }
        d_cart[t * 2] = cx;
        d_cart[t * 2 + 1] = cy;
        m = fmaxf(fabsf(cx), fabsf(cy));
    }
#pragma unroll
    for (int off = 16; off > 0; off >>= 1)
        m = fmaxf(m, __shfl_down_sync(0xffffffffu, m, off));
    if ((threadIdx.x & 31) == 0)
        atomicMax(&d_maxbits, __float_as_int(m)); // nonneg floats: int order == float order
}

// ---------------- K4: exclusive scan of degrees (single block) ----------------
__global__ void k_scan() {
    const int T = 1024;
    const int CH = (N2 + T - 1) / T;  // 15
    __shared__ int partial[T];
    int t = threadIdx.x;
    int base = t * CH;
    int local[CH];
    int s = 0;
#pragma unroll
    for (int i = 0; i < CH; i++) {
        int idx = base + i;
        int v = (idx < N2) ? d_deg[idx] : 0;
        local[i] = s;
        s += v;
    }
    partial[t] = s;
    __syncthreads();
    for (int d = 1; d < T; d <<= 1) {
        int v = (t >= d) ? partial[t - d] : 0;
        __syncthreads();
        partial[t] += v;
        __syncthreads();
    }
    int offset = (t > 0) ? partial[t - 1] : 0;
#pragma unroll
    for (int i = 0; i < CH; i++) {
        int idx = base + i;
        if (idx < N2) d_off[idx] = offset + local[i];
    }
}

// ---------------- K5: CSR fill + per-edge hidden MLP (relu) ----------------
__global__ void k_fill(const int* __restrict__ ei, const float* __restrict__ w2a,
                       const float* __restrict__ b2a) {
    int t = blockIdx.x * blockDim.x + threadIdx.x;
    if (t >= EE) return;
    int r2 = ei[t] >> 1, c2 = ei[EE + t] >> 1;
    if (r2 == c2) return;   // masked: goes to dummy segment, dropped
    int pos = atomicAdd(&d_cursor[r2], 1);
    int slot = d_off[r2] + pos;
    d_edst[slot] = c2;
    float maxv = __int_as_float(d_maxbits);
    float inv = 0.5f / maxv;
    float ea0 = fmaf(d_cart[t * 2],     inv, 0.5f);
    float ea1 = fmaf(d_cart[t * 2 + 1], inv, 0.5f);
    float* hp = d_hid + (size_t)slot * 25;
#pragma unroll
    for (int h = 0; h < 25; h++) {
        float v = fmaf(ea0, __ldg(w2a + h), fmaf(ea1, __ldg(w2a + 25 + h), __ldg(b2a + h)));
        hp[h] = fmaxf(v, 0.f);
    }
}

// ---------------- K6: y GEMM: (15000x32) @ (32x1664), 128x64 tiles ----------------
// y[r, h*64+o] = sum_i x2[r,i]*w2b[h,i*64+o] (h<25);  y[r,25*64+o] = sum_i x2[r,i]*b2b[i*64+o]
__global__ void k_ygemm(const float* __restrict__ w2b, const float* __restrict__ b2b) {
    __shared__ float As[32][136];   // [k][m], padded
    __shared__ float Bs[32][64];    // [k][n]
    int tid = threadIdx.x;
    int m0 = blockIdx.y * 128, n0 = blockIdx.x * 64;
    for (int i = tid; i < 128 * 32; i += 256) {
        int m = i >> 5, k = i & 31;
        int gm = m0 + m;
        As[k][m] = (gm < N2) ? d_x2[gm * 32 + k] : 0.f;
    }
    for (int i = tid; i < 32 * 64; i += 256) {
        int k = i >> 6, n = i & 63;
        int j = n0 + n;
        int h = j >> 6, o = j & 63;
        Bs[k][n] = (h < 25) ? __ldg(w2b + h * 2048 + k * 64 + o)
                            : __ldg(b2b + k * 64 + o);
    }
    __syncthreads();
    int tx = tid & 15, ty = tid >> 4;   // tx: n (16*4=64), ty: m (16*8=128)
    float acc[8][4] = {};
#pragma unroll
    for (int k = 0; k < 32; k++) {
        float a[8], b[4];
#pragma unroll
        for (int m = 0; m < 8; m++) a[m] = As[k][ty * 8 + m];
#pragma unroll
        for (int n = 0; n < 4; n++) b[n] = Bs[k][tx * 4 + n];
#pragma unroll
        for (int m = 0; m < 8; m++)
#pragma unroll
            for (int n = 0; n < 4; n++) acc[m][n] = fmaf(a[m], b[n], acc[m][n]);
    }
#pragma unroll
    for (int m = 0; m < 8; m++) {
        int gm = m0 + ty * 8 + m;
        if (gm < N2) {
#pragma unroll
            for (int n = 0; n < 4; n++)
                d_y[(size_t)gm * YW + n0 + tx * 4 + n] = acc[m][n];
        }
    }
}

// ---------------- K7: layer-2 edge aggregation, CSR by source (block per node) ----------------
__global__ void __launch_bounds__(64) k_edge2csr() {
    int r = blockIdx.x;
    int deg = d_deg[r];
    if (deg == 0) return;
    __shared__ float Ys[YW];
    int tid = threadIdx.x;
    const float4* ysrc = (const float4*)(d_y + (size_t)r * YW);
    float4* ydst = (float4*)Ys;
#pragma unroll
    for (int i = tid; i < YW / 4; i += 64) ydst[i] = ysrc[i];
    __syncthreads();
    int off = d_off[r];
    for (int k = 0; k < deg; k++) {
        int slot = off + k;
        int c2 = d_edst[slot];
        const float* hp = d_hid + (size_t)slot * 25;
        float s = Ys[1600 + tid];
#pragma unroll
        for (int h = 0; h < 25; h++)
            s = fmaf(__ldg(hp + h), Ys[h * 64 + tid], s);
        atomicAdd(d_acc2 + c2 * 64 + tid, s);
    }
}

// ---------------- K8: fused layer-2 node update + pool2 + global mean scatter ----------------
__global__ void k_node2pool(const float* __restrict__ root2, const float* __restrict__ bias2,
                            const int* __restrict__ batch) {
    int idx = blockIdx.x * blockDim.x + threadIdx.x;
    if (idx >= N3 * 64) return;
    int q = idx >> 6, o = idx & 63;
    float v[2];
#pragma unroll
    for (int j = 0; j < 2; j++) {
        int c = 2 * q + j;
        float cnt = fmaxf((float)d_cnt2[c], 1.f);
        float t = d_acc2[c * 64 + o] / cnt + __ldg(bias2 + o);
#pragma unroll
        for (int i = 0; i < 32; i++)
            t = fmaf(d_x2[c * 32 + i], __ldg(root2 + i * 64 + o), t);
        v[j] = eluf(t);
    }
    float m = fmaxf(v[0], v[1]);
    int g = __ldg(batch + 4 * q);   // batch3[q] = batch[4q]
    atomicAdd(d_gsum + g * 64 + o, m);
    if (o == 0) atomicAdd(d_gcnt + g, 1);
}

// ---------------- K9: MLP head + log_softmax (one block per graph) ----------------
__global__ void k_head(const float* __restrict__ fc1_w, const float* __restrict__ fc1_b,
                       const float* __restrict__ fc2_w, const float* __restrict__ fc2_b,
                       float* __restrict__ out) {
    int g = blockIdx.x;
    int t = threadIdx.x;
    __shared__ float m[64];
    __shared__ float a[128];
    __shared__ float logits[10];
    if (t < 64)
        m[t] = d_gsum[g * 64 + t] / fmaxf((float)d_gcnt[g], 1.f);
    __syncthreads();
    float aj = __ldg(fc1_b + t);
#pragma unroll
    for (int i = 0; i < 64; i++)
        aj = fmaf(m[i], __ldg(fc1_w + i * 128 + t), aj);
    a[t] = eluf(aj);
    __syncthreads();
    if (t < 10) {
        float l = __ldg(fc2_b + t);
#pragma unroll 8
        for (int j = 0; j < 128; j++)
            l = fmaf(a[j], __ldg(fc2_w + j * 10 + t), l);
        logits[t] = l;
    }
    __syncthreads();
    if (t == 0) {
        float mx = -1e30f;
#pragma unroll
        for (int k = 0; k < 10; k++) mx = fmaxf(mx, logits[k]);
        float se = 0.f;
#pragma unroll
        for (int k = 0; k < 10; k++) se += expf(logits[k] - mx);
        float lse = logf(se) + mx;
#pragma unroll
        for (int k = 0; k < 10; k++) out[g * 10 + k] = logits[k] - lse;
    }
}

// ---------------- launcher ----------------
extern "C" void kernel_launch(void* const* d_in, const int* in_sizes, int n_in,
                              void* d_out, int out_size) {
    const float* x      = (const float*)d_in[0];
    const float* eattr  = (const float*)d_in[1];
    const float* pos    = (const float*)d_in[2];
    const float* w1a    = (const float*)d_in[3];
    const float* b1a    = (const float*)d_in[4];
    const float* w1b    = (const float*)d_in[5];
    const float* b1b    = (const float*)d_in[6];
    const float* root1  = (const float*)d_in[7];
    const float* bias1  = (const float*)d_in[8];
    const float* w2a    = (const float*)d_in[9];
    const float* b2a    = (const float*)d_in[10];
    const float* w2b    = (const float*)d_in[11];
    const float* b2b    = (const float*)d_in[12];
    const float* root2  = (const float*)d_in[13];
    const float* bias2  = (const float*)d_in[14];
    const float* fc1_w  = (const float*)d_in[15];
    const float* fc1_b  = (const float*)d_in[16];
    const float* fc2_w  = (const float*)d_in[17];
    const float* fc2_b  = (const float*)d_in[18];
    const int*   ei     = (const int*)d_in[19];
    const int*   batch  = (const int*)d_in[20];
    float* out = (float*)d_out;

    k_zero<<<512, 256>>>();
    k_edge1<<<(EE * 32 + 255) / 256, 256>>>(x, eattr, w1a, b1a, w1b, b1b, ei);
    k_node1pool<<<(N2 * 32 + 255) / 256, 256>>>(x, root1, bias1, pos);
    k_geom<<<(EE + 255) / 256, 256>>>(ei);
    k_scan<<<1, 1024>>>();
    k_fill<<<(EE + 255) / 256, 256>>>(ei, w2a, b2a);
    {
        dim3 grid(YW / 64, (N2 + 127) / 128);
        k_ygemm<<<grid, 256>>>(w2b, b2b);
    }
    k_edge2csr<<<N2, 64>>>();
    k_node2pool<<<(N3 * 64 + 255) / 256, 256>>>(root2, bias2, batch);
    k_pool_unused_dummy: ;
    k_head<<<GG, 128>>>(fc1_w, fc1_b, fc2_w, fc2_b, out);
}